// round 6
// baseline (speedup 1.0000x reference)
#include <cuda_runtime.h>
#include <cuda_bf16.h>
#include <math.h>
#include <stdint.h>

#define H 256
#define BM 64
#define MAXN 500000
#define MAXB 1024

// scratch (device globals: allocation-free rule)
__device__ float    g_sum[MAXB * H];
__device__ float    g_att[MAXB * H];
__device__ unsigned g_maxE[MAXB * H];
__device__ float    g_den[MAXB];
__device__ int      g_seg[MAXB + 1];
__device__ int      g_is64;
__device__ uint2    g_Wpk[128 * H];   // W1 prepacked: per kpair (hi bf16x2, lo bf16x2)

// ---------------- helpers ----------------

__device__ __forceinline__ uint32_t bf2_pack(float a, float b) {
    __nv_bfloat162 h = __floats2bfloat162_rn(a, b);  // .x = a (low half)
    return *reinterpret_cast<uint32_t*>(&h);
}

__device__ __forceinline__ float bf_res(float a) {
    return a - __bfloat162float(__float2bfloat16_rn(a));  // exact in fp32
}

__device__ __forceinline__ void mma_bf16(float c[4], const uint32_t a[4],
                                         uint32_t b0, uint32_t b1) {
    asm volatile(
        "mma.sync.aligned.m16n8k16.row.col.f32.bf16.bf16.f32 "
        "{%0,%1,%2,%3}, {%4,%5,%6,%7}, {%8,%9}, {%0,%1,%2,%3};\n"
        : "+f"(c[0]), "+f"(c[1]), "+f"(c[2]), "+f"(c[3])
        : "r"(a[0]), "r"(a[1]), "r"(a[2]), "r"(a[3]), "r"(b0), "r"(b1));
}

__device__ __forceinline__ float tanh_fast(float z) {
    float e = __expf(2.0f * z);
    return 1.0f - 2.0f / (e + 1.0f);
}

// order-preserving float->uint encoding for atomicMax
__device__ __forceinline__ unsigned enc_f(float f) {
    unsigned b = __float_as_uint(f);
    return (b & 0x80000000u) ? ~b : (b | 0x80000000u);
}
#define ENC_NEG_INF 0x007FFFFFu   // enc(-inf)

// ---------------- kernel 0: detect batch dtype (int32 vs int64) ----------------
__global__ void detect_kernel(const void* __restrict__ batch, int n, int B) {
    const long long* b64 = (const long long*)batch;
    int i0 = n / 2 - 1; if (i0 < 0) i0 = 0;
    int i1 = n / 4;     if (i1 >= n / 2) i1 = i0;
    long long v0 = b64[i0];
    long long v1 = b64[i1];
    g_is64 = (v0 >= 0 && v0 < B && v1 >= 0 && v1 < B) ? 1 : 0;
}

__device__ __forceinline__ int read_batch(const void* p, int i, int is64) {
    return is64 ? (int)((const long long*)p)[i] : ((const int*)p)[i];
}

// ---------------- kernel 0b: init accumulators ----------------
__global__ void init_kernel(int B) {
    int i = blockIdx.x * 256 + threadIdx.x;
    if (i < B * H) {
        g_sum[i] = 0.0f;
        g_att[i] = 0.0f;
        g_maxE[i] = ENC_NEG_INF;
    }
    if (i < B) g_den[i] = 0.0f;
}

// ---------------- kernel 0c: prepack W1 (hi/lo bf16x2 per kpair) ----------------
__global__ void prep_kernel(const float* __restrict__ W1) {
    int kp = blockIdx.x;          // 0..127
    int nn = threadIdx.x;         // 0..255
    float w0 = W1[(2 * kp) * H + nn];
    float w1 = W1[(2 * kp + 1) * H + nn];
    g_Wpk[kp * H + nn] = make_uint2(bf2_pack(w0, w1),
                                    bf2_pack(bf_res(w0), bf_res(w1)));
}

// ---------------- kernel 1: segment boundaries (for counts) ----------------
__global__ void seg_kernel(const void* __restrict__ batch, int n, int B) {
    int i = blockIdx.x * blockDim.x + threadIdx.x;
    if (i >= n) return;
    int is64 = g_is64;
    int b = read_batch(batch, i, is64);
    b = b < 0 ? 0 : (b >= B ? B - 1 : b);
    if (i == 0) {
        for (int bb = 0; bb <= b; ++bb) g_seg[bb] = 0;
    } else {
        int pb = read_batch(batch, i - 1, is64);
        pb = pb < 0 ? 0 : (pb >= B ? B - 1 : pb);
        if (pb != b)
            for (int bb = pb + 1; bb <= b; ++bb) g_seg[bb] = i;
    }
    if (i == n - 1) {
        for (int bb = b + 1; bb <= B; ++bb) g_seg[bb] = n;
    }
}

// ---------------- kernel 2: fused scores + pooling ----------------
// Per CTA: 64 nodes. GEMM s = tanh(x@W1+b1)@W2 via bf16 3-term split MMA,
// then e = exp(s) (shift-free: |s| <= 16), then one pass over the x tile
// (L2-hot) accumulating segment sum/max/attn/den via global atomics.
// X smem: interleaved [row][16 words]: pair p at word 4*(p&3)+2*(p>>2), +1 = lo.
// W smem: uint2[8][260] (word stride 520 = 8 mod 32 -> conflict-free LDS.64).
__global__ void __launch_bounds__(256)
score_kernel(const float* __restrict__ x, const void* __restrict__ batch,
             const float* __restrict__ b1, const float* __restrict__ W2,
             int n) {
    __shared__ uint32_t Xint[BM * 16];
    __shared__ uint2    Wint[8 * 260];
    __shared__ float    b1s[H];
    __shared__ float    w2s[H];
    __shared__ float    ssh[BM * 4];
    __shared__ float    se[BM];
    __shared__ int      sbid[BM];

    const int tid   = threadIdx.x;
    const int lane  = tid & 31;
    const int warp  = tid >> 5;
    const int warpM = warp >> 2;   // 0..1
    const int warpN = warp & 3;    // 0..3
    const int gid   = lane >> 2;   // 0..7
    const int tig   = lane & 3;    // 0..3
    const long long m0 = (long long)blockIdx.x * BM;

    b1s[tid] = b1[tid];
    w2s[tid] = W2[tid];

    const int xr = tid >> 2;     // 0..63
    const int xc = tid & 3;      // 0..3
    const bool xok = (m0 + xr < n);
    const float* xrow = x + (m0 + xr) * (long long)H;

    // X store slots for pairs 2*xc, 2*xc+1
    const int ws0 = 4 * ((2 * xc) & 3) + 2 * ((2 * xc) >> 2);
    const int ws1 = 4 * ((2 * xc + 1) & 3) + 2 * ((2 * xc + 1) >> 2);

    // prefetch stage 0
    uint2 wreg[8];
    #pragma unroll
    for (int j = 0; j < 8; ++j) wreg[j] = g_Wpk[j * H + tid];
    float4 xv = make_float4(0.f, 0.f, 0.f, 0.f);
    if (xok) xv = *(const float4*)(xrow + xc * 4);

    float acc[2][8][4];
    #pragma unroll
    for (int mt = 0; mt < 2; ++mt)
        #pragma unroll
        for (int nt = 0; nt < 8; ++nt)
            #pragma unroll
            for (int c = 0; c < 4; ++c) acc[mt][nt][c] = 0.0f;

    for (int kt = 0; kt < 16; ++kt) {
        __syncthreads();   // previous stage consumed
        #pragma unroll
        for (int j = 0; j < 8; ++j) Wint[j * 260 + tid] = wreg[j];
        {
            int base = xr * 16;
            *(uint2*)&Xint[base + ws0] =
                make_uint2(bf2_pack(xv.x, xv.y), bf2_pack(bf_res(xv.x), bf_res(xv.y)));
            *(uint2*)&Xint[base + ws1] =
                make_uint2(bf2_pack(xv.z, xv.w), bf2_pack(bf_res(xv.z), bf_res(xv.w)));
        }
        if (kt < 15) {
            #pragma unroll
            for (int j = 0; j < 8; ++j) wreg[j] = g_Wpk[((kt + 1) * 8 + j) * H + tid];
            xv = make_float4(0.f, 0.f, 0.f, 0.f);
            if (xok) xv = *(const float4*)(xrow + (kt + 1) * 16 + xc * 4);
        }
        __syncthreads();

        uint32_t ah[2][4], al[2][4];
        #pragma unroll
        for (int mt = 0; mt < 2; ++mt) {
            int r0 = warpM * 32 + mt * 16 + gid;
            uint4 q0 = *(const uint4*)&Xint[r0 * 16 + 4 * tig];
            uint4 q1 = *(const uint4*)&Xint[(r0 + 8) * 16 + 4 * tig];
            ah[mt][0] = q0.x; al[mt][0] = q0.y;
            ah[mt][2] = q0.z; al[mt][2] = q0.w;
            ah[mt][1] = q1.x; al[mt][1] = q1.y;
            ah[mt][3] = q1.z; al[mt][3] = q1.w;
        }
        #pragma unroll
        for (int nt = 0; nt < 8; ++nt) {
            int cB = warpN * 64 + nt * 8 + gid;
            uint2 bp0 = Wint[tig * 260 + cB];        // (hi, lo) kpair tig
            uint2 bp1 = Wint[(tig + 4) * 260 + cB];  // (hi, lo) kpair tig+4
            mma_bf16(acc[0][nt], ah[0], bp0.x, bp1.x);
            mma_bf16(acc[1][nt], ah[1], bp0.x, bp1.x);
            mma_bf16(acc[0][nt], al[0], bp0.x, bp1.x);
            mma_bf16(acc[1][nt], al[1], bp0.x, bp1.x);
            mma_bf16(acc[0][nt], ah[0], bp0.y, bp1.y);
            mma_bf16(acc[1][nt], ah[1], bp0.y, bp1.y);
        }
    }

    // epilogue: s_row = sum_cols tanh(z + b1) * w2 (b2 dropped: softmax shift-invariant)
    #pragma unroll
    for (int mt = 0; mt < 2; ++mt) {
        float p0 = 0.0f, p1 = 0.0f;
        #pragma unroll
        for (int nt = 0; nt < 8; ++nt) {
            int c0 = warpN * 64 + nt * 8 + 2 * tig;
            float w0 = w2s[c0], w1v = w2s[c0 + 1];
            float e0 = b1s[c0], e1 = b1s[c0 + 1];
            p0 += w0 * tanh_fast(acc[mt][nt][0] + e0) + w1v * tanh_fast(acc[mt][nt][1] + e1);
            p1 += w0 * tanh_fast(acc[mt][nt][2] + e0) + w1v * tanh_fast(acc[mt][nt][3] + e1);
        }
        p0 += __shfl_xor_sync(0xffffffffu, p0, 1);
        p0 += __shfl_xor_sync(0xffffffffu, p0, 2);
        p1 += __shfl_xor_sync(0xffffffffu, p1, 1);
        p1 += __shfl_xor_sync(0xffffffffu, p1, 2);
        if (tig == 0) {
            int row0 = warpM * 32 + mt * 16 + gid;
            ssh[row0 * 4 + warpN]       = p0;
            ssh[(row0 + 8) * 4 + warpN] = p1;
        }
    }
    __syncthreads();

    // per-row exp + batch id + denominator
    if (tid < BM) {
        long long i = m0 + tid;
        if (i < n) {
            float s = ssh[tid * 4] + ssh[tid * 4 + 1] + ssh[tid * 4 + 2] + ssh[tid * 4 + 3];
            float e = __expf(s);
            se[tid] = e;
            int b = read_batch(batch, (int)i, g_is64);
            sbid[tid] = b;
            atomicAdd(&g_den[b], e);
        } else {
            sbid[tid] = -1;
        }
    }
    __syncthreads();

    // pooling pass: thread = column tid; x tile re-read (L2-hot)
    int rmax = (int)((n - m0) < (long long)BM ? (n - m0) : BM);
    int cur = sbid[0];
    float psum = 0.0f, patt = 0.0f, pmax = -INFINITY;
    const float* xcol = x + m0 * (long long)H + tid;
    for (int r = 0; r < rmax; ++r) {
        int b = sbid[r];
        if (b != cur) {
            atomicAdd(&g_sum[cur * H + tid], psum);
            atomicAdd(&g_att[cur * H + tid], patt);
            atomicMax(&g_maxE[cur * H + tid], enc_f(pmax));
            psum = 0.0f; patt = 0.0f; pmax = -INFINITY; cur = b;
        }
        float v = xcol[(long long)r * H];
        psum += v;
        patt += v * se[r];
        pmax = fmaxf(pmax, v);
    }
    atomicAdd(&g_sum[cur * H + tid], psum);
    atomicAdd(&g_att[cur * H + tid], patt);
    atomicMax(&g_maxE[cur * H + tid], enc_f(pmax));
}

// ---------------- kernel 3: finalize output ----------------
__global__ void finalize_kernel(float* __restrict__ out, int B) {
    int b = blockIdx.x;
    int c = threadIdx.x;
    int cnt = g_seg[b + 1] - g_seg[b];
    float* orow = out + (long long)b * (3 * H);
    if (cnt > 0) {
        float inv = 1.0f / (float)cnt;
        orow[c] = g_sum[b * H + c] * inv;
        unsigned e = g_maxE[b * H + c];
        orow[H + c] = (e & 0x80000000u) ? __uint_as_float(e ^ 0x80000000u)
                                        : __uint_as_float(~e);
        orow[2 * H + c] = g_att[b * H + c] / g_den[b];
    } else {
        orow[c] = 0.0f;
        orow[H + c] = 0.0f;
        orow[2 * H + c] = 0.0f;
    }
}

// ---------------- launch ----------------
extern "C" void kernel_launch(void* const* d_in, const int* in_sizes, int n_in,
                              void* d_out, int out_size) {
    const float* x     = (const float*)d_in[0];
    const void*  batch = d_in[1];
    const float* W1    = (const float*)d_in[2];
    const float* b1    = (const float*)d_in[3];
    const float* W2    = (const float*)d_in[4];
    float*       out   = (float*)d_out;

    int n = in_sizes[1];
    int B = out_size / (3 * H);

    detect_kernel<<<1, 1>>>(batch, n, B);
    init_kernel<<<(B * H + 255) / 256, 256>>>(B);
    prep_kernel<<<128, 256>>>(W1);
    seg_kernel<<<(n + 255) / 256, 256>>>(batch, n, B);
    score_kernel<<<(n + BM - 1) / BM, 256>>>(x, batch, b1, W2, n);
    finalize_kernel<<<B, 256>>>(out, B);
}

// round 7
// speedup vs baseline: 1.0350x; 1.0350x over previous
#include <cuda_runtime.h>
#include <cuda_bf16.h>
#include <math.h>
#include <stdint.h>

#define H 256
#define BM 64
#define MAXN 500000
#define MAXB 1024

// scratch (device globals: allocation-free rule)
__device__ float g_e[MAXN];           // exp(score) per node (shift-free)
__device__ float g_den[MAXB];         // softmax denominator per segment
__device__ int   g_seg[MAXB + 1];
__device__ int   g_is64;
__device__ uint2 g_Wpk[128 * H];      // W1 prepacked: per kpair (hi bf16x2, lo bf16x2)

// ---------------- helpers ----------------

__device__ __forceinline__ uint32_t bf2_pack(float a, float b) {
    __nv_bfloat162 h = __floats2bfloat162_rn(a, b);  // .x = a (low half)
    return *reinterpret_cast<uint32_t*>(&h);
}

__device__ __forceinline__ float bf_res(float a) {
    return a - __bfloat162float(__float2bfloat16_rn(a));  // exact in fp32
}

__device__ __forceinline__ void mma_bf16(float c[4], const uint32_t a[4],
                                         uint32_t b0, uint32_t b1) {
    asm volatile(
        "mma.sync.aligned.m16n8k16.row.col.f32.bf16.bf16.f32 "
        "{%0,%1,%2,%3}, {%4,%5,%6,%7}, {%8,%9}, {%0,%1,%2,%3};\n"
        : "+f"(c[0]), "+f"(c[1]), "+f"(c[2]), "+f"(c[3])
        : "r"(a[0]), "r"(a[1]), "r"(a[2]), "r"(a[3]), "r"(b0), "r"(b1));
}

__device__ __forceinline__ float tanh_fast(float z) {
    float e = __expf(2.0f * z);
    return 1.0f - 2.0f / (e + 1.0f);
}

// ---------------- kernel 0: detect batch dtype (int32 vs int64) ----------------
__global__ void detect_kernel(const void* __restrict__ batch, int n, int B) {
    const long long* b64 = (const long long*)batch;
    int i0 = n / 2 - 1; if (i0 < 0) i0 = 0;
    int i1 = n / 4;     if (i1 >= n / 2) i1 = i0;
    long long v0 = b64[i0];
    long long v1 = b64[i1];
    g_is64 = (v0 >= 0 && v0 < B && v1 >= 0 && v1 < B) ? 1 : 0;
}

__device__ __forceinline__ int read_batch(const void* p, int i, int is64) {
    return is64 ? (int)((const long long*)p)[i] : ((const int*)p)[i];
}

// ---------------- kernel 0b: init denominators + prepack W1 ----------------
__global__ void init_kernel(int B) {
    int i = blockIdx.x * 256 + threadIdx.x;
    if (i < B) g_den[i] = 0.0f;
}

__global__ void prep_kernel(const float* __restrict__ W1) {
    int kp = blockIdx.x;          // 0..127 kpair
    int nn = threadIdx.x;         // 0..255 output column
    float w0 = W1[(2 * kp) * H + nn];
    float w1 = W1[(2 * kp + 1) * H + nn];
    g_Wpk[kp * H + nn] = make_uint2(bf2_pack(w0, w1),
                                    bf2_pack(bf_res(w0), bf_res(w1)));
}

// ---------------- kernel 1: segment boundaries ----------------
__global__ void seg_kernel(const void* __restrict__ batch, int n, int B) {
    int i = blockIdx.x * blockDim.x + threadIdx.x;
    if (i >= n) return;
    int is64 = g_is64;
    int b = read_batch(batch, i, is64);
    b = b < 0 ? 0 : (b >= B ? B - 1 : b);
    if (i == 0) {
        for (int bb = 0; bb <= b; ++bb) g_seg[bb] = 0;
    } else {
        int pb = read_batch(batch, i - 1, is64);
        pb = pb < 0 ? 0 : (pb >= B ? B - 1 : pb);
        if (pb != b)
            for (int bb = pb + 1; bb <= b; ++bb) g_seg[bb] = i;
    }
    if (i == n - 1) {
        for (int bb = b + 1; bb <= B; ++bb) g_seg[bb] = n;
    }
}

// ---------------- kernel 2: attention scores -> exp + denom ----------------
// s[i] = tanh(x[i,:] @ W1 + b1) @ W2  (b2 dropped: softmax shift-invariant)
// e[i] = exp(s[i])  — safe shift-free: |s| <= sum|W2| <= 16.
// CTA: 64 nodes x 256 hidden; 8 warps = 2(M) x 4(N), warp tile 32x64.
// bf16 3-term split MMA: Z = Xh*Wh + Xl*Wh + Xh*Wl (rel err ~2^-16).
// X smem interleaved [row][16 words]: pair p -> word 4*(p&3)+2*(p>>2), +1 = lo
//   -> A fragment = one LDS.128 per 16-row group (conflict-free).
// W smem uint2[8][260]: 8B stride 520 words = 8 mod 32 -> conflict-free LDS.64.
__global__ void __launch_bounds__(256)
score_kernel(const float* __restrict__ x, const void* __restrict__ batch,
             const float* __restrict__ b1, const float* __restrict__ W2,
             int n) {
    __shared__ uint32_t Xint[BM * 16];
    __shared__ uint2    Wint[8 * 260];
    __shared__ float    b1s[H];
    __shared__ float    w2s[H];
    __shared__ float    ssh[BM * 4];

    const int tid   = threadIdx.x;
    const int lane  = tid & 31;
    const int warp  = tid >> 5;
    const int warpM = warp >> 2;   // 0..1
    const int warpN = warp & 3;    // 0..3
    const int gid   = lane >> 2;   // 0..7
    const int tig   = lane & 3;    // 0..3
    const long long m0 = (long long)blockIdx.x * BM;

    b1s[tid] = b1[tid];
    w2s[tid] = W2[tid];

    const int xr = tid >> 2;     // 0..63
    const int xc = tid & 3;      // 0..3
    const bool xok = (m0 + xr < n);
    const float* xrow = x + (m0 + xr) * (long long)H;

    const int ws0 = 4 * ((2 * xc) & 3) + 2 * ((2 * xc) >> 2);
    const int ws1 = 4 * ((2 * xc + 1) & 3) + 2 * ((2 * xc + 1) >> 2);

    // prefetch stage 0
    uint2 wreg[8];
    #pragma unroll
    for (int j = 0; j < 8; ++j) wreg[j] = g_Wpk[j * H + tid];
    float4 xv = make_float4(0.f, 0.f, 0.f, 0.f);
    if (xok) xv = *(const float4*)(xrow + xc * 4);

    float acc[2][8][4];
    #pragma unroll
    for (int mt = 0; mt < 2; ++mt)
        #pragma unroll
        for (int nt = 0; nt < 8; ++nt)
            #pragma unroll
            for (int c = 0; c < 4; ++c) acc[mt][nt][c] = 0.0f;

    for (int kt = 0; kt < 16; ++kt) {
        __syncthreads();   // previous stage consumed
        #pragma unroll
        for (int j = 0; j < 8; ++j) Wint[j * 260 + tid] = wreg[j];
        {
            int base = xr * 16;
            *(uint2*)&Xint[base + ws0] =
                make_uint2(bf2_pack(xv.x, xv.y), bf2_pack(bf_res(xv.x), bf_res(xv.y)));
            *(uint2*)&Xint[base + ws1] =
                make_uint2(bf2_pack(xv.z, xv.w), bf2_pack(bf_res(xv.z), bf_res(xv.w)));
        }
        if (kt < 15) {
            #pragma unroll
            for (int j = 0; j < 8; ++j) wreg[j] = g_Wpk[((kt + 1) * 8 + j) * H + tid];
            xv = make_float4(0.f, 0.f, 0.f, 0.f);
            if (xok) xv = *(const float4*)(xrow + (kt + 1) * 16 + xc * 4);
        }
        __syncthreads();

        uint32_t ah[2][4], al[2][4];
        #pragma unroll
        for (int mt = 0; mt < 2; ++mt) {
            int r0 = warpM * 32 + mt * 16 + gid;
            uint4 q0 = *(const uint4*)&Xint[r0 * 16 + 4 * tig];
            uint4 q1 = *(const uint4*)&Xint[(r0 + 8) * 16 + 4 * tig];
            ah[mt][0] = q0.x; al[mt][0] = q0.y;
            ah[mt][2] = q0.z; al[mt][2] = q0.w;
            ah[mt][1] = q1.x; al[mt][1] = q1.y;
            ah[mt][3] = q1.z; al[mt][3] = q1.w;
        }
        #pragma unroll
        for (int nt = 0; nt < 8; ++nt) {
            int cB = warpN * 64 + nt * 8 + gid;
            uint2 bp0 = Wint[tig * 260 + cB];        // (hi, lo) kpair tig
            uint2 bp1 = Wint[(tig + 4) * 260 + cB];  // (hi, lo) kpair tig+4
            mma_bf16(acc[0][nt], ah[0], bp0.x, bp1.x);
            mma_bf16(acc[1][nt], ah[1], bp0.x, bp1.x);
            mma_bf16(acc[0][nt], al[0], bp0.x, bp1.x);
            mma_bf16(acc[1][nt], al[1], bp0.x, bp1.x);
            mma_bf16(acc[0][nt], ah[0], bp0.y, bp1.y);
            mma_bf16(acc[1][nt], ah[1], bp0.y, bp1.y);
        }
    }

    // epilogue: s_row = sum_cols tanh(z + b1) * w2
    #pragma unroll
    for (int mt = 0; mt < 2; ++mt) {
        float p0 = 0.0f, p1 = 0.0f;
        #pragma unroll
        for (int nt = 0; nt < 8; ++nt) {
            int c0 = warpN * 64 + nt * 8 + 2 * tig;
            float w0 = w2s[c0], w1v = w2s[c0 + 1];
            float e0 = b1s[c0], e1 = b1s[c0 + 1];
            p0 += w0 * tanh_fast(acc[mt][nt][0] + e0) + w1v * tanh_fast(acc[mt][nt][1] + e1);
            p1 += w0 * tanh_fast(acc[mt][nt][2] + e0) + w1v * tanh_fast(acc[mt][nt][3] + e1);
        }
        p0 += __shfl_xor_sync(0xffffffffu, p0, 1);
        p0 += __shfl_xor_sync(0xffffffffu, p0, 2);
        p1 += __shfl_xor_sync(0xffffffffu, p1, 1);
        p1 += __shfl_xor_sync(0xffffffffu, p1, 2);
        if (tig == 0) {
            int row0 = warpM * 32 + mt * 16 + gid;
            ssh[row0 * 4 + warpN]       = p0;
            ssh[(row0 + 8) * 4 + warpN] = p1;
        }
    }
    __syncthreads();
    if (tid < BM && m0 + tid < n) {
        float s = ssh[tid * 4] + ssh[tid * 4 + 1] + ssh[tid * 4 + 2] + ssh[tid * 4 + 3];
        float e = __expf(s);
        g_e[m0 + tid] = e;
        int b = read_batch(batch, (int)(m0 + tid), g_is64);
        atomicAdd(&g_den[b], e);
    }
}

// ---------------- kernel 3: fused mean/max/attn pooling ----------------
// one CTA per segment; 256 threads = 4 node-rows x 64 float4-columns
__global__ void pool_kernel(const float* __restrict__ x, float* __restrict__ out, int B) {
    int b = blockIdx.x;
    int start = g_seg[b], end = g_seg[b + 1];
    int len = end - start;
    float* orow = out + (long long)b * (3 * H);

    if (len <= 0) {
        for (int j = threadIdx.x; j < 3 * H; j += 256) orow[j] = 0.0f;
        return;
    }

    int r = threadIdx.x >> 6;   // 0..3
    int c = threadIdx.x & 63;   // 0..63 (float4 col)

    float4 sum = make_float4(0.f, 0.f, 0.f, 0.f);
    float4 att = make_float4(0.f, 0.f, 0.f, 0.f);
    float4 mx  = make_float4(-INFINITY, -INFINITY, -INFINITY, -INFINITY);

    for (int i = start + r; i < end; i += 4) {
        float ei = g_e[i];
        float4 xv = *(const float4*)(x + (long long)i * H + c * 4);
        sum.x += xv.x; sum.y += xv.y; sum.z += xv.z; sum.w += xv.w;
        mx.x = fmaxf(mx.x, xv.x); mx.y = fmaxf(mx.y, xv.y);
        mx.z = fmaxf(mx.z, xv.z); mx.w = fmaxf(mx.w, xv.w);
        att.x += ei * xv.x; att.y += ei * xv.y;
        att.z += ei * xv.z; att.w += ei * xv.w;
    }

    __shared__ float4 shsum[4][64];
    __shared__ float4 shmax[4][64];
    __shared__ float4 shatt[4][64];
    shsum[r][c] = sum; shmax[r][c] = mx; shatt[r][c] = att;
    __syncthreads();

    if (r == 0) {
        #pragma unroll
        for (int rr = 1; rr < 4; ++rr) {
            float4 s2 = shsum[rr][c], m2 = shmax[rr][c], a2 = shatt[rr][c];
            sum.x += s2.x; sum.y += s2.y; sum.z += s2.z; sum.w += s2.w;
            mx.x = fmaxf(mx.x, m2.x); mx.y = fmaxf(mx.y, m2.y);
            mx.z = fmaxf(mx.z, m2.z); mx.w = fmaxf(mx.w, m2.w);
            att.x += a2.x; att.y += a2.y; att.z += a2.z; att.w += a2.w;
        }
        float invc = 1.0f / (float)len;
        float invd = 1.0f / g_den[b];
        float4 mean = make_float4(sum.x * invc, sum.y * invc, sum.z * invc, sum.w * invc);
        float4 attn = make_float4(att.x * invd, att.y * invd, att.z * invd, att.w * invd);
        *(float4*)(orow + c * 4)         = mean;
        *(float4*)(orow + H + c * 4)     = mx;
        *(float4*)(orow + 2 * H + c * 4) = attn;
    }
}

// ---------------- launch ----------------
extern "C" void kernel_launch(void* const* d_in, const int* in_sizes, int n_in,
                              void* d_out, int out_size) {
    const float* x     = (const float*)d_in[0];
    const void*  batch = d_in[1];
    const float* W1    = (const float*)d_in[2];
    const float* b1    = (const float*)d_in[3];
    const float* W2    = (const float*)d_in[4];
    float*       out   = (float*)d_out;

    int n = in_sizes[1];
    int B = out_size / (3 * H);

    detect_kernel<<<1, 1>>>(batch, n, B);
    init_kernel<<<(B + 255) / 256, 256>>>(B);
    prep_kernel<<<128, 256>>>(W1);
    seg_kernel<<<(n + 255) / 256, 256>>>(batch, n, B);
    score_kernel<<<(n + BM - 1) / BM, 256>>>(x, batch, b1, W2, n);
    pool_kernel<<<B, 256>>>(x, out, B);
}